// round 15
// baseline (speedup 1.0000x reference)
#include <cuda_runtime.h>
#include <cuda_fp16.h>
#include <cstdint>

// Problem constants
#define Bv 4
#define Sv 2048
#define Hv 16
#define DKv 128
#define DMv 2048
#define Mv (Bv * Sv)  // 8192

// ---------------- device scratch (static, allocation-free) ----------------
__device__ __half g_Xh [Mv * DMv];
__device__ __half g_Wqh[DMv * DMv];
__device__ __half g_Wkh[DMv * DMv];
__device__ __half g_Wvh[DMv * DMv];
__device__ __half g_Woh[DMv * DMv];
__device__ __half g_Q  [Mv * DMv];
__device__ __half g_K  [Mv * DMv];
__device__ __half g_V  [Mv * DMv];
__device__ __half g_Ch [Mv * DMv];

// ---------------- cp.async helpers ----------------
__device__ __forceinline__ void cp16(void* s, const void* g) {
    unsigned int sa = (unsigned int)__cvta_generic_to_shared(s);
    asm volatile("cp.async.cg.shared.global [%0], [%1], 16;\n" :: "r"(sa), "l"(g));
}
__device__ __forceinline__ void cp_commit() { asm volatile("cp.async.commit_group;\n"); }
template <int N>
__device__ __forceinline__ void cp_wait() { asm volatile("cp.async.wait_group %0;\n" :: "n"(N)); }

__device__ __forceinline__ uint32_t smem_to_u32(const void* smem_ptr) {
    uint32_t addr;
    asm("{ .reg .u64 tmp; cvta.to.shared.u64 tmp, %1; cvt.u32.u64 %0, tmp; }"
        : "=r"(addr) : "l"(smem_ptr));
    return addr;
}

// ---------------- mma.sync / ldmatrix helpers ----------------
__device__ __forceinline__ void ldsm4(uint32_t* r, uint32_t a) {
    asm volatile("ldmatrix.sync.aligned.m8n8.x4.shared.b16 {%0,%1,%2,%3}, [%4];"
        : "=r"(r[0]), "=r"(r[1]), "=r"(r[2]), "=r"(r[3]) : "r"(a));
}
__device__ __forceinline__ void ldsm4t(uint32_t* r, uint32_t a) {
    asm volatile("ldmatrix.sync.aligned.m8n8.x4.trans.shared.b16 {%0,%1,%2,%3}, [%4];"
        : "=r"(r[0]), "=r"(r[1]), "=r"(r[2]), "=r"(r[3]) : "r"(a));
}
__device__ __forceinline__ void mma_16816(float* c, uint32_t a0, uint32_t a1, uint32_t a2,
                                          uint32_t a3, uint32_t b0, uint32_t b1) {
    asm volatile(
        "mma.sync.aligned.m16n8k16.row.col.f32.f16.f16.f32 "
        "{%0,%1,%2,%3}, {%4,%5,%6,%7}, {%8,%9}, {%0,%1,%2,%3};"
        : "+f"(c[0]), "+f"(c[1]), "+f"(c[2]), "+f"(c[3])
        : "r"(a0), "r"(a1), "r"(a2), "r"(a3), "r"(b0), "r"(b1));
}

// ---------------- fp32 -> fp16 convert (vector 8) ----------------
__global__ void f2h_kernel(const float4* __restrict__ in, uint4* __restrict__ out, int n8) {
    int i = blockIdx.x * blockDim.x + threadIdx.x;
    int stride = gridDim.x * blockDim.x;
    for (; i < n8; i += stride) {
        float4 a = in[i * 2], b = in[i * 2 + 1];
        __half2 h0 = __floats2half2_rn(a.x, a.y);
        __half2 h1 = __floats2half2_rn(a.z, a.w);
        __half2 h2 = __floats2half2_rn(b.x, b.y);
        __half2 h3 = __floats2half2_rn(b.z, b.w);
        uint4 o;
        o.x = *(unsigned int*)&h0; o.y = *(unsigned int*)&h1;
        o.z = *(unsigned int*)&h2; o.w = *(unsigned int*)&h3;
        out[i] = o;
    }
}

// ---------------- GEMM: block 128x128, 4 warps (2x2), warp tile 64x64, BK=64, 3-stage ----------------
// Raw mma.sync + ldmatrix mainloop. C[M,N] = A[M,K] * B[N,K]^T.
#define BK 64
#define KSTR 72
#define BUFH (128 * KSTR)
#define NSTG 3
#define GEMM_SMEM (NSTG * 2 * BUFH * 2)  // 110592 bytes -> 2 CTAs/SM

__device__ __forceinline__ void load_tiles(
    const __half* __restrict__ A, const __half* __restrict__ B, int Kdim,
    int bm, int bn, __half* As, __half* Bs, int stg, int k0, int tid) {
#pragma unroll
    for (int t = 0; t < 8; t++) {
        int v = tid + t * 128;
        int r = v >> 3;
        int c = (v & 7) * 8;
        cp16(&As[stg * BUFH + r * KSTR + c], &A[(size_t)(bm + r) * Kdim + k0 + c]);
    }
#pragma unroll
    for (int t = 0; t < 8; t++) {
        int v = tid + t * 128;
        int r = v >> 3;
        int c = (v & 7) * 8;
        cp16(&Bs[stg * BUFH + r * KSTR + c], &B[(size_t)(bn + r) * Kdim + k0 + c]);
    }
    cp_commit();
}

// acc[i][j][4]: i = m16 block (4), j = n8 block (8) -> warp tile 64x64
__device__ __forceinline__ void gemm_mainloop_raw(
    const __half* __restrict__ A, const __half* __restrict__ B, int Kdim,
    int bm, int bn, __half* As, __half* Bs, uint32_t As_u, uint32_t Bs_u,
    float acc[4][8][4], int tid, int wr, int wc, int lane) {
    const int KT = Kdim / BK;
    load_tiles(A, B, Kdim, bm, bn, As, Bs, 0, 0, tid);
    load_tiles(A, B, Kdim, bm, bn, As, Bs, 1, BK, tid);

    // per-thread ldmatrix address offsets (halves)
    const int arow = wr * 64 + (lane & 7) + ((lane >> 3) & 1) * 8;  // + i*16
    const int acol = (lane >> 4) * 8;                                // + kk
    const int brow = wc * 64 + (lane & 7);                           // + j*8
    const int bcol = (lane >> 3) * 8;                                // + g*32

    int stg = 0;
    for (int kt = 0; kt < KT; ++kt) {
        cp_wait<1>();
        __syncthreads();
        if (kt + 2 < KT) {
            int ns = stg + 2; if (ns >= NSTG) ns -= NSTG;
            load_tiles(A, B, Kdim, bm, bn, As, Bs, ns, (kt + 2) * BK, tid);
        } else {
            cp_commit();  // keep group accounting in step for cp_wait<1>
        }

        const uint32_t Ab_u = As_u + (uint32_t)stg * BUFH * 2;
        const uint32_t Bb_u = Bs_u + (uint32_t)stg * BUFH * 2;
#pragma unroll
        for (int g = 0; g < 2; g++) {            // two k32 groups per k-tile
            uint32_t bfr[8][4];
#pragma unroll
            for (int j = 0; j < 8; j++)
                ldsm4(bfr[j], Bb_u + (uint32_t)((brow + j * 8) * KSTR + g * 32 + bcol) * 2);
#pragma unroll
            for (int ks = 0; ks < 2; ks++) {     // two k16 steps per group
                uint32_t afr[4][4];
#pragma unroll
                for (int i = 0; i < 4; i++)
                    ldsm4(afr[i], Ab_u +
                          (uint32_t)((arow + i * 16) * KSTR + g * 32 + ks * 16 + acol) * 2);
#pragma unroll
                for (int i = 0; i < 4; i++)
#pragma unroll
                    for (int j = 0; j < 8; j++)
                        mma_16816(acc[i][j], afr[i][0], afr[i][1], afr[i][2], afr[i][3],
                                  bfr[j][2 * ks], bfr[j][2 * ks + 1]);
            }
        }
        if (++stg == NSTG) stg = 0;
    }
}

// ---------------- fused QKV projection (direct split-head fp16 fragment epilogue) ----------------
// grid (16, 64, 3): x = head (BN==DKv==128), y = row tile, z = projection
__global__ __launch_bounds__(128, 2) void gemm_qkv_kernel(
    const __half* __restrict__ X,
    const __half* __restrict__ Wq, const __half* __restrict__ Wk, const __half* __restrict__ Wv,
    __half* __restrict__ Q, __half* __restrict__ K, __half* __restrict__ V) {
    extern __shared__ char smem[];
    __half* As = (__half*)smem;
    __half* Bs = As + NSTG * BUFH;
    const uint32_t As_u = smem_to_u32(As);
    const uint32_t Bs_u = As_u + NSTG * BUFH * 2;

    const __half* Bw = (blockIdx.z == 0) ? Wq : (blockIdx.z == 1) ? Wk : Wv;
    __half* O = (blockIdx.z == 0) ? Q : (blockIdx.z == 1) ? K : V;

    const int tid = threadIdx.x, warp = tid >> 5, lane = tid & 31;
    const int wr = warp >> 1, wc = warp & 1;
    const int bm = blockIdx.y * 128, bn = blockIdx.x * 128;

    float acc[4][8][4];
#pragma unroll
    for (int i = 0; i < 4; i++)
#pragma unroll
        for (int j = 0; j < 8; j++)
            acc[i][j][0] = acc[i][j][1] = acc[i][j][2] = acc[i][j][3] = 0.0f;

    gemm_mainloop_raw(X, Bw, DMv, bm, bn, As, Bs, As_u, Bs_u, acc, tid, wr, wc, lane);

    // epilogue: direct fragment stores (half2), split-head layout
    const int b = bm >> 11, s0 = bm & (Sv - 1), h = blockIdx.x;
    __half* Ob = O + (((size_t)(b * Hv + h)) * Sv + s0) * DKv;
#pragma unroll
    for (int i = 0; i < 4; i++) {
        int r0 = wr * 64 + i * 16 + (lane >> 2);
#pragma unroll
        for (int j = 0; j < 8; j++) {
            int d = wc * 64 + j * 8 + 2 * (lane & 3);
            __half2 lo = __floats2half2_rn(acc[i][j][0], acc[i][j][1]);
            __half2 hi = __floats2half2_rn(acc[i][j][2], acc[i][j][3]);
            *(__half2*)&Ob[r0 * DKv + d] = lo;
            *(__half2*)&Ob[(r0 + 8) * DKv + d] = hi;
        }
    }
}

// ---------------- output projection GEMM (f32 out, direct fragment epilogue) ----------------
__global__ __launch_bounds__(128, 2) void gemm_out_kernel(
    const __half* __restrict__ A, const __half* __restrict__ Bw, float* __restrict__ C) {
    extern __shared__ char smem[];
    __half* As = (__half*)smem;
    __half* Bs = As + NSTG * BUFH;
    const uint32_t As_u = smem_to_u32(As);
    const uint32_t Bs_u = As_u + NSTG * BUFH * 2;

    const int tid = threadIdx.x, warp = tid >> 5, lane = tid & 31;
    const int wr = warp >> 1, wc = warp & 1;
    const int bm = blockIdx.y * 128, bn = blockIdx.x * 128;

    float acc[4][8][4];
#pragma unroll
    for (int i = 0; i < 4; i++)
#pragma unroll
        for (int j = 0; j < 8; j++)
            acc[i][j][0] = acc[i][j][1] = acc[i][j][2] = acc[i][j][3] = 0.0f;

    gemm_mainloop_raw(A, Bw, DMv, bm, bn, As, Bs, As_u, Bs_u, acc, tid, wr, wc, lane);

#pragma unroll
    for (int i = 0; i < 4; i++) {
        int r0 = bm + wr * 64 + i * 16 + (lane >> 2);
#pragma unroll
        for (int j = 0; j < 8; j++) {
            int c = bn + wc * 64 + j * 8 + 2 * (lane & 3);
            *(float2*)&C[(size_t)r0 * DMv + c]       = make_float2(acc[i][j][0], acc[i][j][1]);
            *(float2*)&C[(size_t)(r0 + 8) * DMv + c] = make_float2(acc[i][j][2], acc[i][j][3]);
        }
    }
}

// ---------------- flash attention v3: FA2 register-resident (mma.sync + ldmatrix) ----------------
#define QSTR 136   // halves stride: 128 + 8
#define FLASH_SMEM (3 * 64 * QSTR * 2)   // 52224 bytes

__global__ __launch_bounds__(128, 2) void flash_kernel(
    const __half* __restrict__ Q, const __half* __restrict__ K,
    const __half* __restrict__ V, __half* __restrict__ Ch,
    const int* __restrict__ um_ptr) {
    extern __shared__ char smem[];
    __half* Qs = (__half*)smem;            // 64 x QSTR
    __half* Ks = Qs + 64 * QSTR;
    __half* Vs = Ks + 64 * QSTR;
    const uint32_t Qs_u = smem_to_u32(Qs);
    const uint32_t Ks_u = Qs_u + 64 * QSTR * 2;
    const uint32_t Vs_u = Ks_u + 64 * QSTR * 2;

    const int tid  = threadIdx.x;
    const int warp = tid >> 5;
    const int lane = tid & 31;
    const int qb = blockIdx.x;
    const int bh = blockIdx.y;
    const int um = *um_ptr;

    const __half* Qb  = Q + ((size_t)bh * Sv + qb * 64) * DKv;
    const __half* Kb0 = K + ((size_t)bh * Sv) * DKv;
    const __half* Vb0 = V + ((size_t)bh * Sv) * DKv;
#pragma unroll
    for (int t = 0; t < 8; t++) {
        int v = tid + t * 128;
        int r = v >> 4, c = (v & 15) * 8;
        *(uint4*)&Qs[r * QSTR + c] = *(const uint4*)&Qb [r * DKv + c];
        *(uint4*)&Ks[r * QSTR + c] = *(const uint4*)&Kb0[r * DKv + c];
        *(uint4*)&Vs[r * QSTR + c] = *(const uint4*)&Vb0[r * DKv + c];
    }
    __syncthreads();

    uint32_t qa[8][4];
    {
        int sub = lane >> 3, i = lane & 7;
        int row = warp * 16 + i + (sub & 1) * 8;
        uint32_t base = Qs_u + (uint32_t)(row * QSTR + (sub >> 1) * 8) * 2;
#pragma unroll
        for (int t = 0; t < 8; t++) ldsm4(qa[t], base + t * 32);
    }

    float O[16][4];
#pragma unroll
    for (int j = 0; j < 16; j++) { O[j][0] = O[j][1] = O[j][2] = O[j][3] = 0.0f; }
    float m_lo = -1e30f, m_hi = -1e30f, l_lo = 0.0f, l_hi = 0.0f;

    const float scale = 0.08838834764831845f;
    const int kb_end = um ? qb : (Sv / 64 - 1);
    const int q_lo = qb * 64 + warp * 16 + (lane >> 2);

    for (int kb = 0; kb <= kb_end; ++kb) {
        if (kb > 0) {
            __syncthreads();
            const __half* Kb = K + ((size_t)bh * Sv + kb * 64) * DKv;
            const __half* Vb = V + ((size_t)bh * Sv + kb * 64) * DKv;
#pragma unroll
            for (int t = 0; t < 8; t++) {
                int v = tid + t * 128;
                int r = v >> 4, c = (v & 15) * 8;
                *(uint4*)&Ks[r * QSTR + c] = *(const uint4*)&Kb[r * DKv + c];
                *(uint4*)&Vs[r * QSTR + c] = *(const uint4*)&Vb[r * DKv + c];
            }
            __syncthreads();
        }

        float sc[8][4];
#pragma unroll
        for (int j = 0; j < 8; j++) { sc[j][0] = sc[j][1] = sc[j][2] = sc[j][3] = 0.0f; }
#pragma unroll
        for (int j = 0; j < 8; j++) {
            uint32_t ka = Ks_u + (uint32_t)((j * 8 + (lane & 7)) * QSTR + (lane >> 3) * 8) * 2;
#pragma unroll
            for (int t2 = 0; t2 < 8; t2 += 2) {
                uint32_t kf[4];
                ldsm4(kf, ka + t2 * 32);
                mma_16816(sc[j], qa[t2][0], qa[t2][1], qa[t2][2], qa[t2][3], kf[0], kf[1]);
                mma_16816(sc[j], qa[t2+1][0], qa[t2+1][1], qa[t2+1][2], qa[t2+1][3], kf[2], kf[3]);
            }
        }

        float nm_lo = -1e30f, nm_hi = -1e30f;
        const bool diag = (um != 0) && (kb == qb);
#pragma unroll
        for (int j = 0; j < 8; j++) {
            sc[j][0] *= scale; sc[j][1] *= scale; sc[j][2] *= scale; sc[j][3] *= scale;
            if (diag) {
                int k0 = kb * 64 + 8 * j + 2 * (lane & 3);
                if (k0     > q_lo)     sc[j][0] = -1e30f;
                if (k0 + 1 > q_lo)     sc[j][1] = -1e30f;
                if (k0     > q_lo + 8) sc[j][2] = -1e30f;
                if (k0 + 1 > q_lo + 8) sc[j][3] = -1e30f;
            }
            nm_lo = fmaxf(nm_lo, fmaxf(sc[j][0], sc[j][1]));
            nm_hi = fmaxf(nm_hi, fmaxf(sc[j][2], sc[j][3]));
        }
        nm_lo = fmaxf(nm_lo, __shfl_xor_sync(0xffffffffu, nm_lo, 1));
        nm_lo = fmaxf(nm_lo, __shfl_xor_sync(0xffffffffu, nm_lo, 2));
        nm_hi = fmaxf(nm_hi, __shfl_xor_sync(0xffffffffu, nm_hi, 1));
        nm_hi = fmaxf(nm_hi, __shfl_xor_sync(0xffffffffu, nm_hi, 2));

        float mn_lo = fmaxf(m_lo, nm_lo), mn_hi = fmaxf(m_hi, nm_hi);
        float al = __expf(m_lo - mn_lo), ah = __expf(m_hi - mn_hi);
        m_lo = mn_lo; m_hi = mn_hi;

        uint32_t pa[4][4];
        float rs_lo = 0.0f, rs_hi = 0.0f;
#pragma unroll
        for (int t = 0; t < 4; t++) {
            int j0 = 2 * t, j1 = 2 * t + 1;
            float e0 = __expf(sc[j0][0] - mn_lo), e1 = __expf(sc[j0][1] - mn_lo);
            float e2 = __expf(sc[j0][2] - mn_hi), e3 = __expf(sc[j0][3] - mn_hi);
            float f0 = __expf(sc[j1][0] - mn_lo), f1 = __expf(sc[j1][1] - mn_lo);
            float f2 = __expf(sc[j1][2] - mn_hi), f3 = __expf(sc[j1][3] - mn_hi);
            rs_lo += e0 + e1 + f0 + f1;
            rs_hi += e2 + e3 + f2 + f3;
            __half2 h;
            h = __floats2half2_rn(e0, e1); pa[t][0] = *(unsigned int*)&h;
            h = __floats2half2_rn(e2, e3); pa[t][1] = *(unsigned int*)&h;
            h = __floats2half2_rn(f0, f1); pa[t][2] = *(unsigned int*)&h;
            h = __floats2half2_rn(f2, f3); pa[t][3] = *(unsigned int*)&h;
        }
        rs_lo += __shfl_xor_sync(0xffffffffu, rs_lo, 1);
        rs_lo += __shfl_xor_sync(0xffffffffu, rs_lo, 2);
        rs_hi += __shfl_xor_sync(0xffffffffu, rs_hi, 1);
        rs_hi += __shfl_xor_sync(0xffffffffu, rs_hi, 2);
        l_lo = l_lo * al + rs_lo;
        l_hi = l_hi * ah + rs_hi;

#pragma unroll
        for (int j = 0; j < 16; j++) {
            O[j][0] *= al; O[j][1] *= al; O[j][2] *= ah; O[j][3] *= ah;
        }

#pragma unroll
        for (int t = 0; t < 4; t++) {
            uint32_t va = Vs_u +
                (uint32_t)((16 * t + (lane & 7) + ((lane >> 3) & 1) * 8) * QSTR +
                           (lane >> 4) * 8) * 2;
#pragma unroll
            for (int jp = 0; jp < 8; jp++) {
                uint32_t vf[4];
                ldsm4t(vf, va + jp * 32);
                mma_16816(O[2*jp],   pa[t][0], pa[t][1], pa[t][2], pa[t][3], vf[0], vf[1]);
                mma_16816(O[2*jp+1], pa[t][0], pa[t][1], pa[t][2], pa[t][3], vf[2], vf[3]);
            }
        }
    }

    const float il = 1.0f / l_lo, ih = 1.0f / l_hi;
    const int b = bh / Hv, h = bh % Hv;
    __half* p_lo = Ch + (size_t)(b * Sv + q_lo) * DMv + h * DKv + 2 * (lane & 3);
    __half* p_hi = p_lo + 8 * (size_t)DMv;
#pragma unroll
    for (int j = 0; j < 16; j++) {
        __half2 lo = __floats2half2_rn(O[j][0] * il, O[j][1] * il);
        __half2 hi = __floats2half2_rn(O[j][2] * ih, O[j][3] * ih);
        *(__half2*)&p_lo[8 * j] = lo;
        *(__half2*)&p_hi[8 * j] = hi;
    }
}

// ---------------- launch ----------------
extern "C" void kernel_launch(void* const* d_in, const int* in_sizes, int n_in,
                              void* d_out, int out_size) {
    const float* x  = (const float*)d_in[0];
    const float* Wq = (const float*)d_in[1];
    const float* Wk = (const float*)d_in[2];
    const float* Wv = (const float*)d_in[3];
    const float* Wo = (const float*)d_in[4];
    const int*   um = (const int*)d_in[5];
    float* out = (float*)d_out;

    __half *Xh, *Wqh, *Wkh, *Wvh, *Woh, *Q, *K, *V, *Ch;
    cudaGetSymbolAddress((void**)&Xh,  g_Xh);
    cudaGetSymbolAddress((void**)&Wqh, g_Wqh);
    cudaGetSymbolAddress((void**)&Wkh, g_Wkh);
    cudaGetSymbolAddress((void**)&Wvh, g_Wvh);
    cudaGetSymbolAddress((void**)&Woh, g_Woh);
    cudaGetSymbolAddress((void**)&Q,   g_Q);
    cudaGetSymbolAddress((void**)&K,   g_K);
    cudaGetSymbolAddress((void**)&V,   g_V);
    cudaGetSymbolAddress((void**)&Ch,  g_Ch);

    f2h_kernel<<<2048, 256>>>((const float4*)x,  (uint4*)Xh,  Mv * DMv / 8);
    f2h_kernel<<<1024, 256>>>((const float4*)Wq, (uint4*)Wqh, DMv * DMv / 8);
    f2h_kernel<<<1024, 256>>>((const float4*)Wk, (uint4*)Wkh, DMv * DMv / 8);
    f2h_kernel<<<1024, 256>>>((const float4*)Wv, (uint4*)Wvh, DMv * DMv / 8);
    f2h_kernel<<<1024, 256>>>((const float4*)Wo, (uint4*)Woh, DMv * DMv / 8);

    cudaFuncSetAttribute(gemm_qkv_kernel, cudaFuncAttributeMaxDynamicSharedMemorySize, GEMM_SMEM);
    cudaFuncSetAttribute(gemm_out_kernel, cudaFuncAttributeMaxDynamicSharedMemorySize, GEMM_SMEM);
    cudaFuncSetAttribute(flash_kernel, cudaFuncAttributeMaxDynamicSharedMemorySize, FLASH_SMEM);

    gemm_qkv_kernel<<<dim3(16, 64, 3), 128, GEMM_SMEM>>>(Xh, Wqh, Wkh, Wvh, Q, K, V);

    flash_kernel<<<dim3(Sv / 64, Bv * Hv), 128, FLASH_SMEM>>>(Q, K, V, Ch, um);

    gemm_out_kernel<<<dim3(16, 64), 128, GEMM_SMEM>>>(Ch, Woh, out);
}

// round 16
// speedup vs baseline: 1.1247x; 1.1247x over previous
#include <cuda_runtime.h>
#include <cuda_fp16.h>
#include <mma.h>
#include <cstdint>

using namespace nvcuda;

// Problem constants
#define Bv 4
#define Sv 2048
#define Hv 16
#define DKv 128
#define DMv 2048
#define Mv (Bv * Sv)  // 8192

// ---------------- device scratch (static, allocation-free) ----------------
__device__ __half g_Xh [Mv * DMv];
__device__ __half g_Wqh[DMv * DMv];
__device__ __half g_Wkh[DMv * DMv];
__device__ __half g_Wvh[DMv * DMv];
__device__ __half g_Woh[DMv * DMv];
__device__ __half g_Q  [Mv * DMv];
__device__ __half g_K  [Mv * DMv];
__device__ __half g_V  [Mv * DMv];
__device__ __half g_Ch [Mv * DMv];

// ---------------- cp.async helpers ----------------
__device__ __forceinline__ void cp16(void* s, const void* g) {
    unsigned int sa = (unsigned int)__cvta_generic_to_shared(s);
    asm volatile("cp.async.cg.shared.global [%0], [%1], 16;\n" :: "r"(sa), "l"(g));
}
__device__ __forceinline__ void cp_commit() { asm volatile("cp.async.commit_group;\n"); }
template <int N>
__device__ __forceinline__ void cp_wait() { asm volatile("cp.async.wait_group %0;\n" :: "n"(N)); }

__device__ __forceinline__ uint32_t smem_to_u32(const void* smem_ptr) {
    uint32_t addr;
    asm("{ .reg .u64 tmp; cvta.to.shared.u64 tmp, %1; cvt.u32.u64 %0, tmp; }"
        : "=r"(addr) : "l"(smem_ptr));
    return addr;
}

// ---------------- mma.sync / ldmatrix helpers (flash) ----------------
__device__ __forceinline__ void ldsm4(uint32_t* r, uint32_t a) {
    asm volatile("ldmatrix.sync.aligned.m8n8.x4.shared.b16 {%0,%1,%2,%3}, [%4];"
        : "=r"(r[0]), "=r"(r[1]), "=r"(r[2]), "=r"(r[3]) : "r"(a));
}
__device__ __forceinline__ void ldsm4t(uint32_t* r, uint32_t a) {
    asm volatile("ldmatrix.sync.aligned.m8n8.x4.trans.shared.b16 {%0,%1,%2,%3}, [%4];"
        : "=r"(r[0]), "=r"(r[1]), "=r"(r[2]), "=r"(r[3]) : "r"(a));
}
__device__ __forceinline__ void mma_16816(float* c, uint32_t a0, uint32_t a1, uint32_t a2,
                                          uint32_t a3, uint32_t b0, uint32_t b1) {
    asm volatile(
        "mma.sync.aligned.m16n8k16.row.col.f32.f16.f16.f32 "
        "{%0,%1,%2,%3}, {%4,%5,%6,%7}, {%8,%9}, {%0,%1,%2,%3};"
        : "+f"(c[0]), "+f"(c[1]), "+f"(c[2]), "+f"(c[3])
        : "r"(a0), "r"(a1), "r"(a2), "r"(a3), "r"(b0), "r"(b1));
}

// ---------------- fp32 -> fp16 convert: all five tensors in ONE launch ----------------
__global__ void f2h_all_kernel(
    const float4* __restrict__ x,  const float4* __restrict__ wq,
    const float4* __restrict__ wk, const float4* __restrict__ wv,
    const float4* __restrict__ wo,
    uint4* __restrict__ xh, uint4* __restrict__ wqh, uint4* __restrict__ wkh,
    uint4* __restrict__ wvh, uint4* __restrict__ woh) {
    const int XC = Mv * DMv / 8;    // 2097152 chunks of 8
    const int WC = DMv * DMv / 8;   // 524288
    const int total = XC + 4 * WC;
    int i = blockIdx.x * blockDim.x + threadIdx.x;
    int stride = gridDim.x * blockDim.x;
    for (; i < total; i += stride) {
        const float4* src; uint4* dst; int off;
        if (i < XC) { src = x; dst = xh; off = i; }
        else {
            int k = i - XC;
            int r = k / WC;
            off = k - r * WC;
            src = (r == 0) ? wq : (r == 1) ? wk : (r == 2) ? wv : wo;
            dst = (r == 0) ? wqh : (r == 1) ? wkh : (r == 2) ? wvh : woh;
        }
        float4 a = src[off * 2], b = src[off * 2 + 1];
        __half2 h0 = __floats2half2_rn(a.x, a.y);
        __half2 h1 = __floats2half2_rn(a.z, a.w);
        __half2 h2 = __floats2half2_rn(b.x, b.y);
        __half2 h3 = __floats2half2_rn(b.z, b.w);
        uint4 o;
        o.x = *(unsigned int*)&h0; o.y = *(unsigned int*)&h1;
        o.z = *(unsigned int*)&h2; o.w = *(unsigned int*)&h3;
        dst[off] = o;
    }
}

// ---------------- GEMM: block 128x128, 4 warps (2x2), warp tile 64x64, BK=64, 3-stage ----------------
// (R13 WMMA mainloop — best measured; do not modify)
#define BK 64
#define KSTR 72
#define BUFH (128 * KSTR)
#define NSTG 3
#define GEMM_SMEM (NSTG * 2 * BUFH * 2)  // 110592 bytes -> 2 CTAs/SM

__device__ __forceinline__ void load_tiles(
    const __half* __restrict__ A, const __half* __restrict__ B, int Kdim,
    int bm, int bn, __half* As, __half* Bs, int stg, int k0, int tid) {
#pragma unroll
    for (int t = 0; t < 8; t++) {
        int v = tid + t * 128;
        int r = v >> 3;
        int c = (v & 7) * 8;
        cp16(&As[stg * BUFH + r * KSTR + c], &A[(size_t)(bm + r) * Kdim + k0 + c]);
    }
#pragma unroll
    for (int t = 0; t < 8; t++) {
        int v = tid + t * 128;
        int r = v >> 3;
        int c = (v & 7) * 8;
        cp16(&Bs[stg * BUFH + r * KSTR + c], &B[(size_t)(bn + r) * Kdim + k0 + c]);
    }
    cp_commit();
}

__device__ __forceinline__ void gemm_mainloop(
    const __half* __restrict__ A, const __half* __restrict__ B, int Kdim,
    int bm, int bn, __half* As, __half* Bs,
    wmma::fragment<wmma::accumulator, 16, 16, 16, float> acc[4][4],
    int tid, int wr, int wc) {
    const int KT = Kdim / BK;
    load_tiles(A, B, Kdim, bm, bn, As, Bs, 0, 0, tid);
    load_tiles(A, B, Kdim, bm, bn, As, Bs, 1, BK, tid);
    int stg = 0;
    for (int kt = 0; kt < KT; ++kt) {
        cp_wait<1>();
        __syncthreads();
        const __half* Ab = &As[stg * BUFH];
        const __half* Bb = &Bs[stg * BUFH];
#pragma unroll
        for (int kk = 0; kk < BK; kk += 16) {
            wmma::fragment<wmma::matrix_b, 16, 16, 16, __half, wmma::col_major> bf[4];
#pragma unroll
            for (int j = 0; j < 4; j++)
                wmma::load_matrix_sync(bf[j], &Bb[(wc * 64 + j * 16) * KSTR + kk], KSTR);
#pragma unroll
            for (int i = 0; i < 4; i++) {
                wmma::fragment<wmma::matrix_a, 16, 16, 16, __half, wmma::row_major> af;
                wmma::load_matrix_sync(af, &Ab[(wr * 64 + i * 16) * KSTR + kk], KSTR);
#pragma unroll
                for (int j = 0; j < 4; j++)
                    wmma::mma_sync(acc[i][j], af, bf[j], acc[i][j]);
            }
        }
        if (kt + 2 < KT) {
            int ns = stg + 2; if (ns >= NSTG) ns -= NSTG;
            load_tiles(A, B, Kdim, bm, bn, As, Bs, ns, (kt + 2) * BK, tid);
        } else {
            cp_commit();
        }
        if (++stg == NSTG) stg = 0;
    }
}

// ---------------- fused QKV projection (direct split-head fp16 epilogue) ----------------
__global__ __launch_bounds__(128, 2) void gemm_qkv_kernel(
    const __half* __restrict__ X,
    const __half* __restrict__ Wq, const __half* __restrict__ Wk, const __half* __restrict__ Wv,
    __half* __restrict__ Q, __half* __restrict__ K, __half* __restrict__ V) {
    extern __shared__ char smem[];
    __half* As = (__half*)smem;
    __half* Bs = As + NSTG * BUFH;

    const __half* Bw = (blockIdx.z == 0) ? Wq : (blockIdx.z == 1) ? Wk : Wv;
    __half* O = (blockIdx.z == 0) ? Q : (blockIdx.z == 1) ? K : V;

    const int tid = threadIdx.x, warp = tid >> 5;
    const int wr = warp >> 1, wc = warp & 1;
    const int bm = blockIdx.y * 128, bn = blockIdx.x * 128;

    wmma::fragment<wmma::accumulator, 16, 16, 16, float> acc[4][4];
#pragma unroll
    for (int i = 0; i < 4; i++)
#pragma unroll
        for (int j = 0; j < 4; j++) wmma::fill_fragment(acc[i][j], 0.0f);

    gemm_mainloop(X, Bw, DMv, bm, bn, As, Bs, acc, tid, wr, wc);

    float* Cs = (float*)smem;  // 128 x 132
    __syncthreads();
#pragma unroll
    for (int i = 0; i < 4; i++)
#pragma unroll
        for (int j = 0; j < 4; j++)
            wmma::store_matrix_sync(&Cs[(wr * 64 + i * 16) * 132 + wc * 64 + j * 16],
                                    acc[i][j], 132, wmma::mem_row_major);
    __syncthreads();

    const int b = bm >> 11, s0 = bm & (Sv - 1), h = blockIdx.x;
    __half* Ob = O + (((size_t)(b * Hv + h)) * Sv + s0) * DKv;
    for (int i = tid; i < 128 * 16; i += 128) {
        int r = i >> 4, d = (i & 15) * 8;
        const float* cp = &Cs[r * 132 + d];
        __half2 p0 = __floats2half2_rn(cp[0], cp[1]);
        __half2 p1 = __floats2half2_rn(cp[2], cp[3]);
        __half2 p2 = __floats2half2_rn(cp[4], cp[5]);
        __half2 p3 = __floats2half2_rn(cp[6], cp[7]);
        uint4 o;
        o.x = *(unsigned int*)&p0; o.y = *(unsigned int*)&p1;
        o.z = *(unsigned int*)&p2; o.w = *(unsigned int*)&p3;
        *(uint4*)&Ob[r * DKv + d] = o;
    }
}

// ---------------- output projection GEMM (f32 out) ----------------
__global__ __launch_bounds__(128, 2) void gemm_out_kernel(
    const __half* __restrict__ A, const __half* __restrict__ Bw, float* __restrict__ C) {
    extern __shared__ char smem[];
    __half* As = (__half*)smem;
    __half* Bs = As + NSTG * BUFH;

    const int tid = threadIdx.x, warp = tid >> 5;
    const int wr = warp >> 1, wc = warp & 1;
    const int bm = blockIdx.y * 128, bn = blockIdx.x * 128;

    wmma::fragment<wmma::accumulator, 16, 16, 16, float> acc[4][4];
#pragma unroll
    for (int i = 0; i < 4; i++)
#pragma unroll
        for (int j = 0; j < 4; j++) wmma::fill_fragment(acc[i][j], 0.0f);

    gemm_mainloop(A, Bw, DMv, bm, bn, As, Bs, acc, tid, wr, wc);

#pragma unroll
    for (int i = 0; i < 4; i++)
#pragma unroll
        for (int j = 0; j < 4; j++) {
            float* cptr = &C[(size_t)(bm + wr * 64 + i * 16) * DMv + bn + wc * 64 + j * 16];
            wmma::store_matrix_sync(cptr, acc[i][j], DMv, wmma::mem_row_major);
        }
}

// ---------------- flash attention v4: FA2 register-resident + cp.async K/V double buffer ----------------
// Grid (S/64, B*H), 128 threads (4 warps). Smem: Q | K0 | V0 | K1 | V1 (each 64 x QSTR halves).
#define QSTR 136
#define FTILE (64 * QSTR)                 // halves per tile
#define FLASH_SMEM (5 * FTILE * 2)        // 87040 bytes -> 2 CTAs/SM

__global__ __launch_bounds__(128, 2) void flash_kernel(
    const __half* __restrict__ Q, const __half* __restrict__ K,
    const __half* __restrict__ V, __half* __restrict__ Ch,
    const int* __restrict__ um_ptr) {
    extern __shared__ char smem[];
    __half* Qs = (__half*)smem;
    const uint32_t Qs_u = smem_to_u32(Qs);

    const int tid  = threadIdx.x;
    const int warp = tid >> 5;
    const int lane = tid & 31;
    const int qb = blockIdx.x;
    const int bh = blockIdx.y;
    const int um = *um_ptr;

    const __half* Qb = Q + ((size_t)bh * Sv + qb * 64) * DKv;
    const __half* Kh = K + ((size_t)bh * Sv) * DKv;
    const __half* Vh = V + ((size_t)bh * Sv) * DKv;

    // prologue: async-load Q + K0 + V0 as one group
#pragma unroll
    for (int t = 0; t < 8; t++) {
        int v = tid + t * 128;
        int r = v >> 4, c = (v & 15) * 8;
        cp16(&Qs[r * QSTR + c],             &Qb[r * DKv + c]);
        cp16(&Qs[FTILE + r * QSTR + c],     &Kh[r * DKv + c]);      // K0
        cp16(&Qs[2 * FTILE + r * QSTR + c], &Vh[r * DKv + c]);      // V0
    }
    cp_commit();

    float O[16][4];
#pragma unroll
    for (int j = 0; j < 16; j++) { O[j][0] = O[j][1] = O[j][2] = O[j][3] = 0.0f; }
    float m_lo = -1e30f, m_hi = -1e30f, l_lo = 0.0f, l_hi = 0.0f;
    uint32_t qa[8][4];

    const float scale = 0.08838834764831845f;
    const int kb_end = um ? qb : (Sv / 64 - 1);
    const int q_lo = qb * 64 + warp * 16 + (lane >> 2);

    for (int kb = 0; kb <= kb_end; ++kb) {
        const int cur = kb & 1;
        // issue next K/V group into the other buffer (safe: it was last read at kb-1,
        // and the trailing __syncthreads() of kb-1 ordered those reads before this issue)
        if (kb + 1 <= kb_end) {
            const __half* Kn = Kh + (size_t)(kb + 1) * 64 * DKv;
            const __half* Vn = Vh + (size_t)(kb + 1) * 64 * DKv;
            __half* Kd = Qs + (1 + 2 * (cur ^ 1)) * FTILE;
            __half* Vd = Kd + FTILE;
#pragma unroll
            for (int t = 0; t < 8; t++) {
                int v = tid + t * 128;
                int r = v >> 4, c = (v & 15) * 8;
                cp16(&Kd[r * QSTR + c], &Kn[r * DKv + c]);
                cp16(&Vd[r * QSTR + c], &Vn[r * DKv + c]);
            }
        }
        cp_commit();
        cp_wait<1>();      // current tile (and Q on kb=0) complete
        __syncthreads();

        const uint32_t Ks_u = Qs_u + (1 + 2 * cur) * FTILE * 2;
        const uint32_t Vs_u = Ks_u + FTILE * 2;

        if (kb == 0) {
            // preload Q a-fragments once
            int sub = lane >> 3, i = lane & 7;
            int row = warp * 16 + i + (sub & 1) * 8;
            uint32_t base = Qs_u + (uint32_t)(row * QSTR + (sub >> 1) * 8) * 2;
#pragma unroll
            for (int t = 0; t < 8; t++) ldsm4(qa[t], base + t * 32);
        }

        // ---- S = Q K^T ----
        float sc[8][4];
#pragma unroll
        for (int j = 0; j < 8; j++) { sc[j][0] = sc[j][1] = sc[j][2] = sc[j][3] = 0.0f; }
#pragma unroll
        for (int j = 0; j < 8; j++) {
            uint32_t ka = Ks_u + (uint32_t)((j * 8 + (lane & 7)) * QSTR + (lane >> 3) * 8) * 2;
#pragma unroll
            for (int t2 = 0; t2 < 8; t2 += 2) {
                uint32_t kf[4];
                ldsm4(kf, ka + t2 * 32);
                mma_16816(sc[j], qa[t2][0], qa[t2][1], qa[t2][2], qa[t2][3], kf[0], kf[1]);
                mma_16816(sc[j], qa[t2+1][0], qa[t2+1][1], qa[t2+1][2], qa[t2+1][3], kf[2], kf[3]);
            }
        }

        // ---- scale + causal mask + row max ----
        float nm_lo = -1e30f, nm_hi = -1e30f;
        const bool diag = (um != 0) && (kb == qb);
#pragma unroll
        for (int j = 0; j < 8; j++) {
            sc[j][0] *= scale; sc[j][1] *= scale; sc[j][2] *= scale; sc[j][3] *= scale;
            if (diag) {
                int k0 = kb * 64 + 8 * j + 2 * (lane & 3);
                if (k0     > q_lo)     sc[j][0] = -1e30f;
                if (k0 + 1 > q_lo)     sc[j][1] = -1e30f;
                if (k0     > q_lo + 8) sc[j][2] = -1e30f;
                if (k0 + 1 > q_lo + 8) sc[j][3] = -1e30f;
            }
            nm_lo = fmaxf(nm_lo, fmaxf(sc[j][0], sc[j][1]));
            nm_hi = fmaxf(nm_hi, fmaxf(sc[j][2], sc[j][3]));
        }
        nm_lo = fmaxf(nm_lo, __shfl_xor_sync(0xffffffffu, nm_lo, 1));
        nm_lo = fmaxf(nm_lo, __shfl_xor_sync(0xffffffffu, nm_lo, 2));
        nm_hi = fmaxf(nm_hi, __shfl_xor_sync(0xffffffffu, nm_hi, 1));
        nm_hi = fmaxf(nm_hi, __shfl_xor_sync(0xffffffffu, nm_hi, 2));

        float mn_lo = fmaxf(m_lo, nm_lo), mn_hi = fmaxf(m_hi, nm_hi);
        float al = __expf(m_lo - mn_lo), ah = __expf(m_hi - mn_hi);
        m_lo = mn_lo; m_hi = mn_hi;

        // ---- P = exp(S - m) ----
        uint32_t pa[4][4];
        float rs_lo = 0.0f, rs_hi = 0.0f;
#pragma unroll
        for (int t = 0; t < 4; t++) {
            int j0 = 2 * t, j1 = 2 * t + 1;
            float e0 = __expf(sc[j0][0] - mn_lo), e1 = __expf(sc[j0][1] - mn_lo);
            float e2 = __expf(sc[j0][2] - mn_hi), e3 = __expf(sc[j0][3] - mn_hi);
            float f0 = __expf(sc[j1][0] - mn_lo), f1 = __expf(sc[j1][1] - mn_lo);
            float f2 = __expf(sc[j1][2] - mn_hi), f3 = __expf(sc[j1][3] - mn_hi);
            rs_lo += e0 + e1 + f0 + f1;
            rs_hi += e2 + e3 + f2 + f3;
            __half2 h;
            h = __floats2half2_rn(e0, e1); pa[t][0] = *(unsigned int*)&h;
            h = __floats2half2_rn(e2, e3); pa[t][1] = *(unsigned int*)&h;
            h = __floats2half2_rn(f0, f1); pa[t][2] = *(unsigned int*)&h;
            h = __floats2half2_rn(f2, f3); pa[t][3] = *(unsigned int*)&h;
        }
        rs_lo += __shfl_xor_sync(0xffffffffu, rs_lo, 1);
        rs_lo += __shfl_xor_sync(0xffffffffu, rs_lo, 2);
        rs_hi += __shfl_xor_sync(0xffffffffu, rs_hi, 1);
        rs_hi += __shfl_xor_sync(0xffffffffu, rs_hi, 2);
        l_lo = l_lo * al + rs_lo;
        l_hi = l_hi * ah + rs_hi;

#pragma unroll
        for (int j = 0; j < 16; j++) {
            O[j][0] *= al; O[j][1] *= al; O[j][2] *= ah; O[j][3] *= ah;
        }

        // ---- O += P V ----
#pragma unroll
        for (int t = 0; t < 4; t++) {
            uint32_t va = Vs_u +
                (uint32_t)((16 * t + (lane & 7) + ((lane >> 3) & 1) * 8) * QSTR +
                           (lane >> 4) * 8) * 2;
#pragma unroll
            for (int jp = 0; jp < 8; jp++) {
                uint32_t vf[4];
                ldsm4t(vf, va + jp * 32);
                mma_16816(O[2*jp],   pa[t][0], pa[t][1], pa[t][2], pa[t][3], vf[0], vf[1]);
                mma_16816(O[2*jp+1], pa[t][0], pa[t][1], pa[t][2], pa[t][3], vf[2], vf[3]);
            }
        }
        __syncthreads();   // all reads of cur done before it is refilled at kb+2
    }

    // ---- epilogue ----
    const float il = 1.0f / l_lo, ih = 1.0f / l_hi;
    const int b = bh / Hv, h = bh % Hv;
    __half* p_lo = Ch + (size_t)(b * Sv + q_lo) * DMv + h * DKv + 2 * (lane & 3);
    __half* p_hi = p_lo + 8 * (size_t)DMv;
#pragma unroll
    for (int j = 0; j < 16; j++) {
        __half2 lo = __floats2half2_rn(O[j][0] * il, O[j][1] * il);
        __half2 hi = __floats2half2_rn(O[j][2] * ih, O[j][3] * ih);
        *(__half2*)&p_lo[8 * j] = lo;
        *(__half2*)&p_hi[8 * j] = hi;
    }
}

// ---------------- launch ----------------
extern "C" void kernel_launch(void* const* d_in, const int* in_sizes, int n_in,
                              void* d_out, int out_size) {
    const float* x  = (const float*)d_in[0];
    const float* Wq = (const float*)d_in[1];
    const float* Wk = (const float*)d_in[2];
    const float* Wv = (const float*)d_in[3];
    const float* Wo = (const float*)d_in[4];
    const int*   um = (const int*)d_in[5];
    float* out = (float*)d_out;

    __half *Xh, *Wqh, *Wkh, *Wvh, *Woh, *Q, *K, *V, *Ch;
    cudaGetSymbolAddress((void**)&Xh,  g_Xh);
    cudaGetSymbolAddress((void**)&Wqh, g_Wqh);
    cudaGetSymbolAddress((void**)&Wkh, g_Wkh);
    cudaGetSymbolAddress((void**)&Wvh, g_Wvh);
    cudaGetSymbolAddress((void**)&Woh, g_Woh);
    cudaGetSymbolAddress((void**)&Q,   g_Q);
    cudaGetSymbolAddress((void**)&K,   g_K);
    cudaGetSymbolAddress((void**)&V,   g_V);
    cudaGetSymbolAddress((void**)&Ch,  g_Ch);

    f2h_all_kernel<<<4096, 256>>>(
        (const float4*)x, (const float4*)Wq, (const float4*)Wk,
        (const float4*)Wv, (const float4*)Wo,
        (uint4*)Xh, (uint4*)Wqh, (uint4*)Wkh, (uint4*)Wvh, (uint4*)Woh);

    cudaFuncSetAttribute(gemm_qkv_kernel, cudaFuncAttributeMaxDynamicSharedMemorySize, GEMM_SMEM);
    cudaFuncSetAttribute(gemm_out_kernel, cudaFuncAttributeMaxDynamicSharedMemorySize, GEMM_SMEM);
    cudaFuncSetAttribute(flash_kernel, cudaFuncAttributeMaxDynamicSharedMemorySize, FLASH_SMEM);

    gemm_qkv_kernel<<<dim3(16, 64, 3), 128, GEMM_SMEM>>>(Xh, Wqh, Wkh, Wvh, Q, K, V);

    flash_kernel<<<dim3(Sv / 64, Bv * Hv), 128, FLASH_SMEM>>>(Q, K, V, Ch, um);

    gemm_out_kernel<<<dim3(16, 64), 128, GEMM_SMEM>>>(Ch, Woh, out);
}